// round 14
// baseline (speedup 1.0000x reference)
#include <cuda_runtime.h>
#include <math_constants.h>

// ============================================================
// ChamferLoss via exact 2-D (x,y)-binned sorted-window NN.
//  - bucket-sort both clouds by (xbin, ybin), 64x64 bins
//  - query kernel, FOUR LANES PER QUERY (8 queries/warp):
//      queries processed in sorted order -> the 8 queries of a warp share
//      nearly identical rect bounds (minimal sub-warp divergence).
//      seed: scan (2r+1)^2 rect, expanding r until non-empty -> d0
//      exact: rect [bcoord(qx+-d0)] x [bcoord(qy+-d0)] (+-1 pad); points
//             outside have |dx|>d0 or |dy|>d0 -> cannot beat best. Exact.
//  - scan_kernel zeroes g_bincnt after use -> no init kernel, 6 launches.
//  - single writer per query into g_dist[orig] -> bit-deterministic.
// ============================================================

#define XB 64
#define YB 64
#define NBINS (XB * YB)              // 4096
#define GRID_LO (-6.0f)
#define INV_BINW (64.0f / 12.0f)
#define MAXPTS 16384
#define LPQ 4                        // lanes per query
#define RED_CTAS 64
#define RED_THREADS 256

__device__ float4 g_sorted[2][MAXPTS];
__device__ int    g_bincnt[2][NBINS];       // zero-init BSS; re-zeroed by scan
__device__ int    g_binstart[2][NBINS + 1];
__device__ int    g_curs[2][NBINS];
__device__ float  g_dist[2 * MAXPTS];
__device__ float  g_part[RED_CTAS];

__device__ __forceinline__ int bcoord(float v) {
    int b = (int)((v - GRID_LO) * INV_BINW);
    return min(max(b, 0), XB - 1);
}

// ---------- 1. histogram by (xbin, ybin) ----------
__global__ void hist_kernel(const float* __restrict__ A,
                            const float* __restrict__ B, int N, int M) {
    int gid = blockIdx.x * blockDim.x + threadIdx.x;
    if (gid >= N + M) return;
    int cl = (gid >= N);
    int i = cl ? gid - N : gid;
    const float* src = cl ? B : A;
    int key = bcoord(src[3 * i]) * YB + bcoord(src[3 * i + 1]);
    atomicAdd(&g_bincnt[cl][key], 1);
}

// ---------- 2. per-cloud exclusive scan over 4096 bins (one CTA) ----------
// Also zeroes g_bincnt for the next graph replay.
__global__ void __launch_bounds__(1024)
scan_kernel() {
    __shared__ int s[1024];
    const int tid = threadIdx.x;
    const int CPT = (2 * NBINS) / 1024;     // 8 flattened bins per thread
    const int base = tid * CPT;

    int c[CPT], sum = 0;
    #pragma unroll
    for (int i = 0; i < CPT; i++) {
        c[i] = ((int*)g_bincnt)[base + i];
        ((int*)g_bincnt)[base + i] = 0;      // reset for next replay
        sum += c[i];
    }
    s[tid] = sum;
    __syncthreads();
    #pragma unroll
    for (int off = 1; off < 1024; off <<= 1) {
        int v = (tid >= off) ? s[tid - off] : 0;
        __syncthreads();
        s[tid] += v;
        __syncthreads();
    }
    // threads [0,512) hold cloud 0, [512,1024) cloud 1 (4096 bins each)
    const int cloud_off = (tid >= 512) ? s[511] : 0;
    int run = (s[tid] - sum) - cloud_off;
    #pragma unroll
    for (int i = 0; i < CPT; i++) {
        int g = base + i;
        int cl = g >> 12, b = g & (NBINS - 1);
        g_binstart[cl][b] = run;
        g_curs[cl][b] = run;
        run += c[i];
    }
    if (tid == 511)  g_binstart[0][NBINS] = s[511];
    if (tid == 1023) g_binstart[1][NBINS] = s[1023] - s[511];
}

// ---------- 3. scatter into (x,y)-sorted order (orig index in .w) ----------
__global__ void scatter_kernel(const float* __restrict__ A,
                               const float* __restrict__ B, int N, int M) {
    int gid = blockIdx.x * blockDim.x + threadIdx.x;
    if (gid >= N + M) return;
    int cl = (gid >= N);
    int i = cl ? gid - N : gid;
    const float* src = cl ? B : A;
    float x = src[3 * i], y = src[3 * i + 1], z = src[3 * i + 2];
    int key = bcoord(x) * YB + bcoord(y);
    int pos = atomicAdd(&g_curs[cl][key], 1);
    g_sorted[cl][pos] = make_float4(x, y, z, __int_as_float(i));
}

// ---------- 4. exact two-phase NN, 4 lanes per query ----------
__global__ void __launch_bounds__(256)
query_kernel(int N, int M) {
    const int gid = blockIdx.x * blockDim.x + threadIdx.x;
    const int qid = gid >> 2;               // query id (sorted order)
    const int sl = gid & (LPQ - 1);         // sub-lane within 4-lane group
    if (qid >= N + M) return;
    const int cl = (qid >= N);
    const int i = cl ? qid - N : qid;
    const int ct = 1 - cl;

    const float4 p = g_sorted[cl][i];       // group-broadcast load
    const float qx = p.x, qy = p.y, qz = p.z;
    const int* __restrict__ bs = g_binstart[ct];
    const float4* __restrict__ pts = g_sorted[ct];
    const int xb = bcoord(qx), yb = bcoord(qy);

    // seed: scan (2r+1)^2 rect, expanding until non-empty
    float best = CUDART_INF_F;
    int r = 1;
    int xlo, xhi, ylo, yhi;
    for (;;) {
        xlo = max(xb - r, 0); xhi = min(xb + r, XB - 1);
        ylo = max(yb - r, 0); yhi = min(yb + r, YB - 1);
        int cnt = 0;
        for (int xr = xlo; xr <= xhi; xr++) {
            const int s = bs[xr * YB + ylo];
            const int e = bs[xr * YB + yhi + 1];
            cnt += e - s;
            for (int k = s + sl; k < e; k += LPQ) {
                float4 t = pts[k];
                float dx = qx - t.x, dy = qy - t.y, dz = qz - t.z;
                best = fminf(best, fmaf(dx, dx, fmaf(dy, dy, dz * dz)));
            }
        }
        if (cnt > 0) break;
        r++;
    }
    best = fminf(best, __shfl_xor_sync(0xFFFFFFFFu, best, 1, LPQ));
    best = fminf(best, __shfl_xor_sync(0xFFFFFFFFu, best, 2, LPQ));

    // exact rect (+-1 bin fp pad); skip if contained in the seed rect
    const float d0 = sqrtf(best);
    const int xlo2 = max(bcoord(qx - d0) - 1, 0);
    const int xhi2 = min(bcoord(qx + d0) + 1, XB - 1);
    const int ylo2 = max(bcoord(qy - d0) - 1, 0);
    const int yhi2 = min(bcoord(qy + d0) + 1, YB - 1);
    if (xlo2 < xlo || xhi2 > xhi || ylo2 < ylo || yhi2 > yhi) {
        for (int xr = xlo2; xr <= xhi2; xr++) {
            const int s = bs[xr * YB + ylo2];
            const int e = bs[xr * YB + yhi2 + 1];
            for (int k = s + sl; k < e; k += LPQ) {
                float4 t = pts[k];
                float dx = qx - t.x, dy = qy - t.y, dz = qz - t.z;
                best = fminf(best, fmaf(dx, dx, fmaf(dy, dy, dz * dz)));
            }
        }
        best = fminf(best, __shfl_xor_sync(0xFFFFFFFFu, best, 1, LPQ));
        best = fminf(best, __shfl_xor_sync(0xFFFFFFFFu, best, 2, LPQ));
    }

    if (sl == 0)
        g_dist[(cl ? N : 0) + __float_as_int(p.w)] = sqrtf(best);
}

// ---------- 5-6. deterministic two-stage sum ----------
__global__ void __launch_bounds__(RED_THREADS)
reduce1_kernel(int total) {
    __shared__ float ssum[RED_THREADS / 32];
    const int per = (total + RED_CTAS - 1) / RED_CTAS;
    const int base = blockIdx.x * per;
    const int end = min(base + per, total);

    float acc = 0.0f;
    for (int i = base + threadIdx.x; i < end; i += RED_THREADS)
        acc += g_dist[i];
    #pragma unroll
    for (int o = 16; o > 0; o >>= 1)
        acc += __shfl_down_sync(0xFFFFFFFFu, acc, o);
    if ((threadIdx.x & 31) == 0) ssum[threadIdx.x >> 5] = acc;
    __syncthreads();
    if (threadIdx.x == 0) {
        float v = 0.0f;
        #pragma unroll
        for (int w = 0; w < RED_THREADS / 32; w++) v += ssum[w];
        g_part[blockIdx.x] = v;
    }
}

__global__ void reduce2_kernel(float* __restrict__ out) {
    float acc = 0.0f;
    #pragma unroll
    for (int k = 0; k < RED_CTAS / 32; k++)
        acc += g_part[threadIdx.x + 32 * k];
    #pragma unroll
    for (int o = 16; o > 0; o >>= 1)
        acc += __shfl_down_sync(0xFFFFFFFFu, acc, o);
    if (threadIdx.x == 0) out[0] = acc * 0.001f;
}

extern "C" void kernel_launch(void* const* d_in, const int* in_sizes, int n_in,
                              void* d_out, int out_size)
{
    const float* A = (const float*)d_in[0];   // target_pc [N,3]
    const float* B = (const float*)d_in[1];   // output_pc [M,3]
    const int N = in_sizes[0] / 3;
    const int M = in_sizes[1] / 3;
    const int total = N + M;

    hist_kernel<<<(total + 255) / 256, 256>>>(A, B, N, M);
    scan_kernel<<<1, 1024>>>();
    scatter_kernel<<<(total + 255) / 256, 256>>>(A, B, N, M);
    query_kernel<<<(total * LPQ + 255) / 256, 256>>>(N, M);  // 4 lanes/query
    reduce1_kernel<<<RED_CTAS, RED_THREADS>>>(total);
    reduce2_kernel<<<1, 32>>>((float*)d_out);
}

// round 15
// speedup vs baseline: 1.0103x; 1.0103x over previous
#include <cuda_runtime.h>
#include <math_constants.h>

// ============================================================
// ChamferLoss via exact 2-D (x,y)-binned NN, warp-batched queries.
//  - bucket-sort both clouds by (xbin, ybin), 64x64 bins
//  - query kernel: ONE WARP per 8 CONSECUTIVE SORTED QUERIES.
//      All 32 lanes scan the group's UNION rect (coalesced float4,
//      warp-uniform bounds); each target tested vs all 8 register-
//      resident queries (load amortization, full lane utilization).
//      seed: union 3x3 (expand while empty) -> per-query d0 (upper bd)
//      exact: union over j of [bcoord(q_j +- d0_j)] (+-1 pad); outside
//             => |dx|>d0_j or |dy|>d0_j for that query => exact.
//  - scan_kernel zeroes g_bincnt after use -> 6 launches, no init.
//  - one writer per query into g_dist[orig] -> bit-deterministic.
// ============================================================

#define XB 64
#define YB 64
#define NBINS (XB * YB)              // 4096
#define GRID_LO (-6.0f)
#define INV_BINW (64.0f / 12.0f)
#define MAXPTS 16384
#define QPG 8                        // queries per warp-group
#define RED_CTAS 64
#define RED_THREADS 256

__device__ float4 g_sorted[2][MAXPTS];
__device__ int    g_bincnt[2][NBINS];       // zero-init BSS; re-zeroed by scan
__device__ int    g_binstart[2][NBINS + 1];
__device__ int    g_curs[2][NBINS];
__device__ float  g_dist[2 * MAXPTS];
__device__ float  g_part[RED_CTAS];

__device__ __forceinline__ int bcoord(float v) {
    int b = (int)((v - GRID_LO) * INV_BINW);
    return min(max(b, 0), XB - 1);
}

// ---------- 1. histogram by (xbin, ybin) ----------
__global__ void hist_kernel(const float* __restrict__ A,
                            const float* __restrict__ B, int N, int M) {
    int gid = blockIdx.x * blockDim.x + threadIdx.x;
    if (gid >= N + M) return;
    int cl = (gid >= N);
    int i = cl ? gid - N : gid;
    const float* src = cl ? B : A;
    int key = bcoord(src[3 * i]) * YB + bcoord(src[3 * i + 1]);
    atomicAdd(&g_bincnt[cl][key], 1);
}

// ---------- 2. per-cloud exclusive scan over 4096 bins (one CTA) ----------
__global__ void __launch_bounds__(1024)
scan_kernel() {
    __shared__ int s[1024];
    const int tid = threadIdx.x;
    const int CPT = (2 * NBINS) / 1024;     // 8 flattened bins per thread
    const int base = tid * CPT;

    int c[CPT], sum = 0;
    #pragma unroll
    for (int i = 0; i < CPT; i++) {
        c[i] = ((int*)g_bincnt)[base + i];
        ((int*)g_bincnt)[base + i] = 0;      // reset for next graph replay
        sum += c[i];
    }
    s[tid] = sum;
    __syncthreads();
    #pragma unroll
    for (int off = 1; off < 1024; off <<= 1) {
        int v = (tid >= off) ? s[tid - off] : 0;
        __syncthreads();
        s[tid] += v;
        __syncthreads();
    }
    const int cloud_off = (tid >= 512) ? s[511] : 0;
    int run = (s[tid] - sum) - cloud_off;
    #pragma unroll
    for (int i = 0; i < CPT; i++) {
        int g = base + i;
        int cl = g >> 12, b = g & (NBINS - 1);
        g_binstart[cl][b] = run;
        g_curs[cl][b] = run;
        run += c[i];
    }
    if (tid == 511)  g_binstart[0][NBINS] = s[511];
    if (tid == 1023) g_binstart[1][NBINS] = s[1023] - s[511];
}

// ---------- 3. scatter into (x,y)-sorted order (orig index in .w) ----------
__global__ void scatter_kernel(const float* __restrict__ A,
                               const float* __restrict__ B, int N, int M) {
    int gid = blockIdx.x * blockDim.x + threadIdx.x;
    if (gid >= N + M) return;
    int cl = (gid >= N);
    int i = cl ? gid - N : gid;
    const float* src = cl ? B : A;
    float x = src[3 * i], y = src[3 * i + 1], z = src[3 * i + 2];
    int key = bcoord(x) * YB + bcoord(y);
    int pos = atomicAdd(&g_curs[cl][key], 1);
    g_sorted[cl][pos] = make_float4(x, y, z, __int_as_float(i));
}

// ---------- 4. warp-batched exact NN (8 queries / warp) ----------
__global__ void __launch_bounds__(256)
query_kernel(int N, int M) {
    const int w = (blockIdx.x * blockDim.x + threadIdx.x) >> 5;
    const int lane = threadIdx.x & 31;
    const int GA = (N + QPG - 1) / QPG;
    const int GB = (M + QPG - 1) / QPG;
    if (w >= GA + GB) return;
    const int cl = (w >= GA);
    const int qbase = (cl ? (w - GA) : w) * QPG;
    const int nq = cl ? M : N;
    const int ct = 1 - cl;
    const int vn = min(QPG, nq - qbase);

    const float4* __restrict__ Q = g_sorted[cl];
    const int* __restrict__ bs = g_binstart[ct];
    const float4* __restrict__ pts = g_sorted[ct];

    // register-resident query batch (broadcast loads; inactive j -> dup 0)
    float qx[QPG], qy[QPG], qz[QPG], best[QPG];
    int minxb = XB - 1, maxxb = 0, minyb = YB - 1, maxyb = 0;
    #pragma unroll
    for (int j = 0; j < QPG; j++) {
        float4 s = Q[qbase + min(j, vn - 1)];
        qx[j] = s.x; qy[j] = s.y; qz[j] = s.z;
        best[j] = CUDART_INF_F;
        int bx = bcoord(s.x), by = bcoord(s.y);
        minxb = min(minxb, bx); maxxb = max(maxxb, bx);
        minyb = min(minyb, by); maxyb = max(maxyb, by);
    }

    // ---- seed: union rect, expand while empty ----
    int r = 1, xlo, xhi, ylo, yhi;
    for (;;) {
        xlo = max(minxb - r, 0); xhi = min(maxxb + r, XB - 1);
        ylo = max(minyb - r, 0); yhi = min(maxyb + r, YB - 1);
        int cnt = 0;
        for (int xr = xlo; xr <= xhi; xr++) {
            const int s = bs[xr * YB + ylo];
            const int e = bs[xr * YB + yhi + 1];
            cnt += e - s;
            for (int k = s + lane; k < e; k += 32) {     // coalesced float4
                float4 t = pts[k];
                #pragma unroll
                for (int j = 0; j < QPG; j++) {
                    float dx = qx[j] - t.x, dy = qy[j] - t.y, dz = qz[j] - t.z;
                    best[j] = fminf(best[j], fmaf(dx, dx, fmaf(dy, dy, dz * dz)));
                }
            }
        }
        if (cnt > 0) break;
        r++;
    }
    #pragma unroll
    for (int j = 0; j < QPG; j++)
        #pragma unroll
        for (int o = 16; o > 0; o >>= 1)
            best[j] = fminf(best[j], __shfl_xor_sync(0xFFFFFFFFu, best[j], o));

    // ---- exact union rect from per-query d0 (+-1 bin fp pad) ----
    int xlo2 = XB - 1, xhi2 = 0, ylo2 = YB - 1, yhi2 = 0;
    #pragma unroll
    for (int j = 0; j < QPG; j++) {
        float d0 = sqrtf(best[j]);
        xlo2 = min(xlo2, bcoord(qx[j] - d0) - 1);
        xhi2 = max(xhi2, bcoord(qx[j] + d0) + 1);
        ylo2 = min(ylo2, bcoord(qy[j] - d0) - 1);
        yhi2 = max(yhi2, bcoord(qy[j] + d0) + 1);
    }
    xlo2 = max(xlo2, 0); xhi2 = min(xhi2, XB - 1);
    ylo2 = max(ylo2, 0); yhi2 = min(yhi2, YB - 1);

    if (xlo2 < xlo || xhi2 > xhi || ylo2 < ylo || yhi2 > yhi) {
        for (int xr = xlo2; xr <= xhi2; xr++) {
            const int s = bs[xr * YB + ylo2];
            const int e = bs[xr * YB + yhi2 + 1];
            for (int k = s + lane; k < e; k += 32) {
                float4 t = pts[k];
                #pragma unroll
                for (int j = 0; j < QPG; j++) {
                    float dx = qx[j] - t.x, dy = qy[j] - t.y, dz = qz[j] - t.z;
                    best[j] = fminf(best[j], fmaf(dx, dx, fmaf(dy, dy, dz * dz)));
                }
            }
        }
        #pragma unroll
        for (int j = 0; j < QPG; j++)
            #pragma unroll
            for (int o = 16; o > 0; o >>= 1)
                best[j] = fminf(best[j], __shfl_xor_sync(0xFFFFFFFFu, best[j], o));
    }

    if (lane == 0) {
        const int off = cl ? N : 0;
        for (int j = 0; j < vn; j++) {
            int orig = __float_as_int(Q[qbase + j].w);
            g_dist[off + orig] = sqrtf(best[j]);
        }
    }
}

// ---------- 5-6. deterministic two-stage sum ----------
__global__ void __launch_bounds__(RED_THREADS)
reduce1_kernel(int total) {
    __shared__ float ssum[RED_THREADS / 32];
    const int per = (total + RED_CTAS - 1) / RED_CTAS;
    const int base = blockIdx.x * per;
    const int end = min(base + per, total);

    float acc = 0.0f;
    for (int i = base + threadIdx.x; i < end; i += RED_THREADS)
        acc += g_dist[i];
    #pragma unroll
    for (int o = 16; o > 0; o >>= 1)
        acc += __shfl_down_sync(0xFFFFFFFFu, acc, o);
    if ((threadIdx.x & 31) == 0) ssum[threadIdx.x >> 5] = acc;
    __syncthreads();
    if (threadIdx.x == 0) {
        float v = 0.0f;
        #pragma unroll
        for (int w = 0; w < RED_THREADS / 32; w++) v += ssum[w];
        g_part[blockIdx.x] = v;
    }
}

__global__ void reduce2_kernel(float* __restrict__ out) {
    float acc = 0.0f;
    #pragma unroll
    for (int k = 0; k < RED_CTAS / 32; k++)
        acc += g_part[threadIdx.x + 32 * k];
    #pragma unroll
    for (int o = 16; o > 0; o >>= 1)
        acc += __shfl_down_sync(0xFFFFFFFFu, acc, o);
    if (threadIdx.x == 0) out[0] = acc * 0.001f;
}

extern "C" void kernel_launch(void* const* d_in, const int* in_sizes, int n_in,
                              void* d_out, int out_size)
{
    const float* A = (const float*)d_in[0];   // target_pc [N,3]
    const float* B = (const float*)d_in[1];   // output_pc [M,3]
    const int N = in_sizes[0] / 3;
    const int M = in_sizes[1] / 3;
    const int total = N + M;

    hist_kernel<<<(total + 255) / 256, 256>>>(A, B, N, M);
    scan_kernel<<<1, 1024>>>();
    scatter_kernel<<<(total + 255) / 256, 256>>>(A, B, N, M);

    const int groups = (N + QPG - 1) / QPG + (M + QPG - 1) / QPG;  // 4096
    query_kernel<<<(groups * 32 + 255) / 256, 256>>>(N, M);

    reduce1_kernel<<<RED_CTAS, RED_THREADS>>>(total);
    reduce2_kernel<<<1, 32>>>((float*)d_out);
}

// round 16
// speedup vs baseline: 2.2770x; 2.2539x over previous
#include <cuda_runtime.h>
#include <math_constants.h>

// ============================================================
// ChamferLoss via exact 2-D (x,y)-binned NN, warp-per-query (32768 warps).
//  hot path: fused single-pass 3x3 seed (6 range loads, 3 rows virtually
//  concatenated -> full lane utilization), warp reduce -> d0, then
//  UNPADDED exact rect [bcoord(q +- d0)] (bcoord is monotone + clamp-
//  consistent with scatter => rect provably contains every point within
//  d0). Rect almost always contained in the 3x3 seed -> done in 1 pass.
//  Rare paths (empty seed / rect escape) use a generic rect scan.
//  scan_kernel self-zeroes g_bincnt -> no init kernel. Deterministic:
//  bin-determined scan sets, one writer per query into g_dist[orig].
// ============================================================

#define XB 64
#define YB 64
#define NBINS (XB * YB)              // 4096
#define GRID_LO (-6.0f)
#define INV_BINW (64.0f / 12.0f)
#define MAXPTS 16384
#define RED_CTAS 64
#define RED_THREADS 256

__device__ float4 g_sorted[2][MAXPTS];
__device__ int    g_bincnt[2][NBINS];       // zero-init BSS; re-zeroed by scan
__device__ int    g_binstart[2][NBINS + 1];
__device__ int    g_curs[2][NBINS];
__device__ float  g_dist[2 * MAXPTS];
__device__ float  g_part[RED_CTAS];

__device__ __forceinline__ int bcoord(float v) {
    int b = (int)((v - GRID_LO) * INV_BINW);
    return min(max(b, 0), XB - 1);
}

// ---------- 1. histogram by (xbin, ybin) ----------
__global__ void hist_kernel(const float* __restrict__ A,
                            const float* __restrict__ B, int N, int M) {
    int gid = blockIdx.x * blockDim.x + threadIdx.x;
    if (gid >= N + M) return;
    int cl = (gid >= N);
    int i = cl ? gid - N : gid;
    const float* src = cl ? B : A;
    int key = bcoord(src[3 * i]) * YB + bcoord(src[3 * i + 1]);
    atomicAdd(&g_bincnt[cl][key], 1);
}

// ---------- 2. per-cloud exclusive scan over 4096 bins (one CTA) ----------
__global__ void __launch_bounds__(1024)
scan_kernel() {
    __shared__ int s[1024];
    const int tid = threadIdx.x;
    const int CPT = (2 * NBINS) / 1024;     // 8 flattened bins per thread
    const int base = tid * CPT;

    int c[CPT], sum = 0;
    #pragma unroll
    for (int i = 0; i < CPT; i++) {
        c[i] = ((int*)g_bincnt)[base + i];
        ((int*)g_bincnt)[base + i] = 0;      // reset for next graph replay
        sum += c[i];
    }
    s[tid] = sum;
    __syncthreads();
    #pragma unroll
    for (int off = 1; off < 1024; off <<= 1) {
        int v = (tid >= off) ? s[tid - off] : 0;
        __syncthreads();
        s[tid] += v;
        __syncthreads();
    }
    const int cloud_off = (tid >= 512) ? s[511] : 0;
    int run = (s[tid] - sum) - cloud_off;
    #pragma unroll
    for (int i = 0; i < CPT; i++) {
        int g = base + i;
        int cl = g >> 12, b = g & (NBINS - 1);
        g_binstart[cl][b] = run;
        g_curs[cl][b] = run;
        run += c[i];
    }
    if (tid == 511)  g_binstart[0][NBINS] = s[511];
    if (tid == 1023) g_binstart[1][NBINS] = s[1023] - s[511];
}

// ---------- 3. scatter into (x,y)-sorted order (orig index in .w) ----------
__global__ void scatter_kernel(const float* __restrict__ A,
                               const float* __restrict__ B, int N, int M) {
    int gid = blockIdx.x * blockDim.x + threadIdx.x;
    if (gid >= N + M) return;
    int cl = (gid >= N);
    int i = cl ? gid - N : gid;
    const float* src = cl ? B : A;
    float x = src[3 * i], y = src[3 * i + 1], z = src[3 * i + 2];
    int key = bcoord(x) * YB + bcoord(y);
    int pos = atomicAdd(&g_curs[cl][key], 1);
    g_sorted[cl][pos] = make_float4(x, y, z, __int_as_float(i));
}

// generic lane-strided rect scan (rare paths)
__device__ __forceinline__ float rect_scan(const int* __restrict__ bs,
                                           const float4* __restrict__ pts,
                                           int xlo, int xhi, int ylo, int yhi,
                                           float qx, float qy, float qz,
                                           int lane, float best) {
    for (int xr = xlo; xr <= xhi; xr++) {
        const int s = bs[xr * YB + ylo];
        const int e = bs[xr * YB + yhi + 1];
        for (int k = s + lane; k < e; k += 32) {
            float4 t = pts[k];
            float dx = qx - t.x, dy = qy - t.y, dz = qz - t.z;
            best = fminf(best, fmaf(dx, dx, fmaf(dy, dy, dz * dz)));
        }
    }
    return best;
}

// ---------- 4. warp-per-query exact NN ----------
__global__ void __launch_bounds__(256)
query_kernel(int N, int M) {
    const int gw = (blockIdx.x * blockDim.x + threadIdx.x) >> 5;
    const int lane = threadIdx.x & 31;
    if (gw >= N + M) return;
    const int cl = (gw >= N);
    const int i = cl ? gw - N : gw;
    const int ct = 1 - cl;

    const float4 p = g_sorted[cl][i];       // broadcast load
    const float qx = p.x, qy = p.y, qz = p.z;
    const int* __restrict__ bs = g_binstart[ct];
    const float4* __restrict__ pts = g_sorted[ct];
    const int bx = bcoord(qx), by = bcoord(qy);

    // ---- fused 3x3 seed: 6 independent range loads, 3 rows concat ----
    const int yloS = max(by - 1, 0), yhiS = min(by + 1, YB - 1);
    const int xloS = max(bx - 1, 0), xhiS = min(bx + 1, XB - 1);
    int s0 = 0, e0 = 0, s1, e1, s2 = 0, e2 = 0;
    if (bx > 0)      { s0 = bs[(bx - 1) * YB + yloS]; e0 = bs[(bx - 1) * YB + yhiS + 1]; }
    s1 = bs[bx * YB + yloS];  e1 = bs[bx * YB + yhiS + 1];
    if (bx < XB - 1) { s2 = bs[(bx + 1) * YB + yloS]; e2 = bs[(bx + 1) * YB + yhiS + 1]; }
    const int n0 = e0 - s0, n1 = e1 - s1;
    const int p1 = n0, p2 = n0 + n1;
    const int tot = p2 + (e2 - s2);

    float best = CUDART_INF_F;
    for (int k = lane; k < tot; k += 32) {   // virtual concat, full lanes
        int idx = (k < p1) ? (s0 + k)
                : (k < p2) ? (s1 + k - p1)
                           : (s2 + k - p2);
        float4 t = pts[idx];
        float dx = qx - t.x, dy = qy - t.y, dz = qz - t.z;
        best = fminf(best, fmaf(dx, dx, fmaf(dy, dy, dz * dz)));
    }
    #pragma unroll
    for (int o = 16; o > 0; o >>= 1)
        best = fminf(best, __shfl_xor_sync(0xFFFFFFFFu, best, o));

    // rare: empty 3x3 -> expand rect until non-empty (gives upper bound d0)
    if (tot == 0) {
        for (int r = 2; ; r++) {
            int xl = max(bx - r, 0), xh = min(bx + r, XB - 1);
            int yl = max(by - r, 0), yh = min(by + r, YB - 1);
            best = rect_scan(bs, pts, xl, xh, yl, yh, qx, qy, qz, lane, best);
            #pragma unroll
            for (int o = 16; o > 0; o >>= 1)
                best = fminf(best, __shfl_xor_sync(0xFFFFFFFFu, best, o));
            if (best < CUDART_INF_F) break;
        }
    }

    // ---- exact rect, UNPADDED (bcoord monotone + clamp-consistent):
    // every point within d0 of q lies in [bcoord(qx-d0),bcoord(qx+d0)] x
    // [bcoord(qy-d0),bcoord(qy+d0)]. If contained in scanned seed -> done.
    const float d0 = sqrtf(best);
    const int xlo2 = bcoord(qx - d0), xhi2 = bcoord(qx + d0);
    const int ylo2 = bcoord(qy - d0), yhi2 = bcoord(qy + d0);
    if (tot == 0 ||
        xlo2 < xloS || xhi2 > xhiS || ylo2 < yloS || yhi2 > yhiS) {
        best = rect_scan(bs, pts, xlo2, xhi2, ylo2, yhi2,
                         qx, qy, qz, lane, best);
        #pragma unroll
        for (int o = 16; o > 0; o >>= 1)
            best = fminf(best, __shfl_xor_sync(0xFFFFFFFFu, best, o));
    }

    if (lane == 0)
        g_dist[(cl ? N : 0) + __float_as_int(p.w)] = sqrtf(best);
}

// ---------- 5-6. deterministic two-stage sum ----------
__global__ void __launch_bounds__(RED_THREADS)
reduce1_kernel(int total) {
    __shared__ float ssum[RED_THREADS / 32];
    const int per = (total + RED_CTAS - 1) / RED_CTAS;
    const int base = blockIdx.x * per;
    const int end = min(base + per, total);

    float acc = 0.0f;
    for (int i = base + threadIdx.x; i < end; i += RED_THREADS)
        acc += g_dist[i];
    #pragma unroll
    for (int o = 16; o > 0; o >>= 1)
        acc += __shfl_down_sync(0xFFFFFFFFu, acc, o);
    if ((threadIdx.x & 31) == 0) ssum[threadIdx.x >> 5] = acc;
    __syncthreads();
    if (threadIdx.x == 0) {
        float v = 0.0f;
        #pragma unroll
        for (int w = 0; w < RED_THREADS / 32; w++) v += ssum[w];
        g_part[blockIdx.x] = v;
    }
}

__global__ void reduce2_kernel(float* __restrict__ out) {
    float acc = 0.0f;
    #pragma unroll
    for (int k = 0; k < RED_CTAS / 32; k++)
        acc += g_part[threadIdx.x + 32 * k];
    #pragma unroll
    for (int o = 16; o > 0; o >>= 1)
        acc += __shfl_down_sync(0xFFFFFFFFu, acc, o);
    if (threadIdx.x == 0) out[0] = acc * 0.001f;
}

extern "C" void kernel_launch(void* const* d_in, const int* in_sizes, int n_in,
                              void* d_out, int out_size)
{
    const float* A = (const float*)d_in[0];   // target_pc [N,3]
    const float* B = (const float*)d_in[1];   // output_pc [M,3]
    const int N = in_sizes[0] / 3;
    const int M = in_sizes[1] / 3;
    const int total = N + M;

    hist_kernel<<<(total + 255) / 256, 256>>>(A, B, N, M);
    scan_kernel<<<1, 1024>>>();
    scatter_kernel<<<(total + 255) / 256, 256>>>(A, B, N, M);
    query_kernel<<<(total * 32 + 255) / 256, 256>>>(N, M);   // warp / query
    reduce1_kernel<<<RED_CTAS, RED_THREADS>>>(total);
    reduce2_kernel<<<1, 32>>>((float*)d_out);
}